// round 14
// baseline (speedup 1.0000x reference)
#include <cuda_runtime.h>
#include <cuda_fp16.h>
#include <cstdint>

// ---------------------------------------------------------------------------
// B=32, T=4096, K=1024 (2H), N=512 (DFF)
// HMMA GEMM, 3 CTAs/SM, 128 threads: warp tile M64 x N32, 4 N-passes of 128.
// R14: R8 pipeline at higher occupancy (12 warps/SM).
// ---------------------------------------------------------------------------
#define BATCH   32
#define TSEQ    4096
#define KDIM    1024
#define NDFF    512
#define MTILE   64
#define KCH     32
#define NCHUNKS 32
#define NPASS   4
#define NTILES  (TSEQ / MTILE)     // 64
#define NCTAS   (BATCH * NTILES)   // 2048

__device__ __align__(128) __half g_Uh[NDFF * KDIM];             // 1 MB fp16 U [f][e]
__device__ __align__(128) float  g_ws[BATCH * NDFF];
__device__ __align__(128) float  g_partial[NCTAS * KDIM];       // 8 MB
__device__ int g_cnt[BATCH];

// Shared layout (bytes)
#define SM_WS   0                       // 512 f
#define SM_V    2048                    // 512 f
#define SM_EN   4096                    // 4*64 f
#define SM_ENF  5120                    // 64 f
#define SM_FLAG 5376                    // int
#define SM_A    8192                    // 3 stages x 4096  = 12288
#define SM_B    20480                   // 3 stages x 8192  = 24576
#define SMEM_TOTAL 45056

#define SWZ(off) ((uint32_t)(off) ^ ((((uint32_t)(off)) >> 3) & 0x70u))

__device__ __forceinline__ uint32_t smem_u32(const void* p) {
    uint32_t a;
    asm("{ .reg .u64 t; cvta.to.shared.u64 t, %1; cvt.u32.u64 %0, t; }"
        : "=r"(a) : "l"(p));
    return a;
}
__device__ __forceinline__ void cp_async16(uint32_t dst, const void* src) {
    asm volatile("cp.async.cg.shared.global [%0], [%1], 16;"
                 :: "r"(dst), "l"(src) : "memory");
}
#define CP_COMMIT() asm volatile("cp.async.commit_group;" ::: "memory")
#define CP_WAIT1()  asm volatile("cp.async.wait_group 1;" ::: "memory")

__device__ __forceinline__ void ldsm4(uint32_t* r4, uint32_t addr) {
    asm volatile("ldmatrix.sync.aligned.m8n8.x4.shared.b16 {%0,%1,%2,%3}, [%4];"
                 : "=r"(r4[0]), "=r"(r4[1]), "=r"(r4[2]), "=r"(r4[3]) : "r"(addr));
}
__device__ __forceinline__ void mma16816(float* c, const uint32_t* a,
                                         uint32_t b0, uint32_t b1) {
    asm volatile(
        "mma.sync.aligned.m16n8k16.row.col.f32.f16.f16.f32 "
        "{%0,%1,%2,%3}, {%4,%5,%6,%7}, {%8,%9}, {%0,%1,%2,%3};"
        : "+f"(c[0]), "+f"(c[1]), "+f"(c[2]), "+f"(c[3])
        : "r"(a[0]), "r"(a[1]), "r"(a[2]), "r"(a[3]), "r"(b0), "r"(b1));
}
__device__ __forceinline__ uint4 cvt8(const float4& x, const float4& y) {
    uint4 u; __half2 t;
    t = __floats2half2_rn(x.x, x.y); u.x = *(uint32_t*)&t;
    t = __floats2half2_rn(x.z, x.w); u.y = *(uint32_t*)&t;
    t = __floats2half2_rn(y.x, y.y); u.z = *(uint32_t*)&t;
    t = __floats2half2_rn(y.z, y.w); u.w = *(uint32_t*)&t;
    return u;
}

// ---------------------------------------------------------------------------
// Fused prep: blocks 0..511 convU, 512..575 ws, 576 zero counters
// ---------------------------------------------------------------------------
__global__ void k_prep(const float* __restrict__ Uw, const float* __restrict__ s,
                       const float* __restrict__ W,  const float* __restrict__ Wb,
                       const float* __restrict__ Ub) {
    int blk = blockIdx.x;
    int tid = threadIdx.x;
    if (blk < 512) {
        int i = blk * 256 + tid;
        float4 v = reinterpret_cast<const float4*>(Uw)[i];
        __half2 p0 = __floats2half2_rn(v.x, v.y);
        __half2 p1 = __floats2half2_rn(v.z, v.w);
        uint2 u;
        u.x = *reinterpret_cast<uint32_t*>(&p0);
        u.y = *reinterpret_cast<uint32_t*>(&p1);
        *reinterpret_cast<uint2*>(&g_Uh[i * 4]) = u;
    } else if (blk < 576) {
        __shared__ float ssh[512];
        int q = blk - 512;
        int b = q >> 1;
        int f = ((q & 1) << 8) + tid;
        ssh[tid]       = s[b * 512 + tid];
        ssh[tid + 256] = s[b * 512 + tid + 256];
        __syncthreads();
        float acc = Wb[f] + Ub[f];
        const float4* Wr = reinterpret_cast<const float4*>(W + (size_t)f * 512);
#pragma unroll 4
        for (int e4 = 0; e4 < 128; e4++) {
            float4 w = Wr[e4];
            acc = fmaf(ssh[e4 * 4 + 0], w.x, acc);
            acc = fmaf(ssh[e4 * 4 + 1], w.y, acc);
            acc = fmaf(ssh[e4 * 4 + 2], w.z, acc);
            acc = fmaf(ssh[e4 * 4 + 3], w.w, acc);
        }
        g_ws[b * 512 + f] = acc;
    } else {
        if (tid < BATCH) g_cnt[tid] = 0;
    }
}

// ---------------------------------------------------------------------------
// Main kernel: 128 threads, 4 warps, warp tile M64 x N32, 3 CTAs/SM.
// Packed smem rows: two 64B k-rows per 128B smem row, SW128-swizzled.
// ---------------------------------------------------------------------------
__global__ __launch_bounds__(128, 3)
void k_main(const float* __restrict__ h, const float* __restrict__ V,
            const float* __restrict__ Vb, float* __restrict__ out) {
    extern __shared__ char smem[];
    const uint32_t sb = smem_u32(smem);
    const int tid  = threadIdx.x;
    const int wid  = tid >> 5;     // = ng, 0..3 (N32 slice)
    const int lane = tid & 31;
    const int b    = blockIdx.x >> 6;

    float* ws_s  = reinterpret_cast<float*>(smem + SM_WS);
    float* V_s   = reinterpret_cast<float*>(smem + SM_V);
    float* en_s  = reinterpret_cast<float*>(smem + SM_EN);
    float* enf_s = reinterpret_cast<float*>(smem + SM_ENF);
    int*   flag  = reinterpret_cast<int*>(smem + SM_FLAG);

    for (int i = tid; i < NDFF; i += 128) {
        ws_s[i] = g_ws[b * NDFF + i];
        V_s[i]  = V[i];
    }
    for (int i = tid; i < 4 * MTILE; i += 128) en_s[i] = 0.f;

    const float* hB = h + (size_t)blockIdx.x * (MTILE * KDIM);

    // A stream map (per chunk: rows tid>>2 and +32, one 16B seg each)
    const int m_0 = tid >> 2, seg = tid & 3;
    const uint32_t a_sts0 = SWZ((m_0 >> 1) * 128 + (m_0 & 1) * 64 + seg * 16);
    const float4* ap0 = reinterpret_cast<const float4*>(hB) + m_0 * 256 + seg * 2;
    const float4* ap1 = ap0 + 32 * 256;

    // B cp.async map: chunk = 128 rows x 64B; it 0..3 steps 32 rows
    const uint32_t bdst0 = a_sts0;
    const uint32_t bsrc0 = (uint32_t)(m_0 * KDIM + seg * 8);   // halves

    // ldsm bases
    const int r = lane & 7;
    const int selA = (lane >> 3) & 1, selK = (lane >> 4) & 1;
    const int m0f = selA * 8 + r;
    const uint32_t abase0 = SWZ((m0f >> 1) * 128 + (m0f & 1) * 64 + selK * 16);
    const int selKb = (lane >> 3) & 1, selNb = (lane >> 4) & 1;
    const int f0f = selNb * 8 + r;
    const uint32_t bbase0 = SWZ((f0f >> 1) * 128 + (f0f & 1) * 64 + selKb * 16)
                            + (uint32_t)wid * 2048;   // N32 slice = 32 rows x 64B

    float4 p00, p01, p10, p11;

    // ======================= four N-passes of 128 =======================
#pragma unroll 1
    for (int np = 0; np < NPASS; np++) {
        const __half* Ub2 = g_Uh + (size_t)(np * 128) * KDIM;

        float acc[4][4][4];
#pragma unroll
        for (int mi = 0; mi < 4; mi++)
#pragma unroll
            for (int ni = 0; ni < 4; ni++)
#pragma unroll
                for (int q = 0; q < 4; q++) acc[mi][ni][q] = 0.f;

        __syncthreads();   // stage ring reuse safe across passes

        // prologue: A chunks 0,1 -> stages 0,1; chunk 2 in regs; B chunks 0,1
        p00 = ap0[0];  p01 = ap0[1];  p10 = ap1[0];  p11 = ap1[1];
        *reinterpret_cast<uint4*>(smem + SM_A + a_sts0)        = cvt8(p00, p01);
        *reinterpret_cast<uint4*>(smem + SM_A + a_sts0 + 2048) = cvt8(p10, p11);
        p00 = ap0[8];  p01 = ap0[9];  p10 = ap1[8];  p11 = ap1[9];
        *reinterpret_cast<uint4*>(smem + SM_A + 4096 + a_sts0)        = cvt8(p00, p01);
        *reinterpret_cast<uint4*>(smem + SM_A + 4096 + a_sts0 + 2048) = cvt8(p10, p11);
        p00 = ap0[16]; p01 = ap0[17]; p10 = ap1[16]; p11 = ap1[17];
#pragma unroll
        for (int c = 0; c < 2; c++) {
            uint32_t dst = sb + SM_B + c * 8192 + bdst0;
            const __half* src = Ub2 + bsrc0 + c * KCH;
#pragma unroll
            for (int it = 0; it < 4; it++)
                cp_async16(dst + it * 2048, src + it * (32 * KDIM));
            CP_COMMIT();
        }

        // ---------------- K mainloop (R8 fragment pipeline) ----------------
#pragma unroll 1
        for (int c = 0; c < NCHUNKS; c++) {
            CP_WAIT1();
            __syncthreads();

            const uint32_t ab  = sb + SM_A + (c % 3) * 4096;
            const uint32_t bbs = sb + SM_B + (c % 3) * 8192;

            // fragment prologue: A[ki=0] x4, B[g=0]
            uint32_t af[2][4][4];
            uint32_t bf[2][4];
#pragma unroll
            for (int mi = 0; mi < 4; mi++)
                ldsm4(af[0][mi], ab + (abase0 + mi * 1024));
            ldsm4(bf[0], bbs + bbase0);

            // future-chunk memory ops under ldsm latency
            if (c + 2 < NCHUNKS) {
                const int st = (c + 2) % 3;
                uint32_t dst = sb + SM_B + st * 8192 + bdst0;
                const __half* src = Ub2 + bsrc0 + (c + 2) * KCH;
#pragma unroll
                for (int it = 0; it < 4; it++)
                    cp_async16(dst + it * 2048, src + it * (32 * KDIM));
                *reinterpret_cast<uint4*>(smem + SM_A + st * 4096 + a_sts0)
                    = cvt8(p00, p01);
                *reinterpret_cast<uint4*>(smem + SM_A + st * 4096 + a_sts0 + 2048)
                    = cvt8(p10, p11);
                if (c + 3 < NCHUNKS) {
                    p00 = ap0[(c + 3) * 8];     p01 = ap0[(c + 3) * 8 + 1];
                    p10 = ap1[(c + 3) * 8];     p11 = ap1[(c + 3) * 8 + 1];
                }
            }
            CP_COMMIT();

            // g = ki*2 + nj stream, 4 groups of 8 MMAs, 1-ahead B ring
#pragma unroll
            for (int g = 0; g < 4; g++) {
                const int ki = g >> 1, nj = g & 1;
                if (g < 3) {
                    const int gk = (g + 1) >> 1, gn = (g + 1) & 1;
                    ldsm4(bf[(g + 1) & 1],
                          bbs + ((bbase0 + gn * 1024) ^ (uint32_t)(gk * 32)));
                }
                if (g == 1) {
#pragma unroll
                    for (int mi = 0; mi < 4; mi++)
                        ldsm4(af[1][mi], ab + ((abase0 + mi * 1024) ^ 32u));
                }
#pragma unroll
                for (int mi = 0; mi < 4; mi++) {
                    mma16816(acc[mi][2 * nj],     af[ki][mi],
                             bf[g & 1][0], bf[g & 1][1]);
                    mma16816(acc[mi][2 * nj + 1], af[ki][mi],
                             bf[g & 1][2], bf[g & 1][3]);
                }
            }
        }

        // ---------------- epilogue: energy partials ----------------
#pragma unroll
        for (int mi = 0; mi < 4; mi++) {
#pragma unroll
            for (int rh = 0; rh < 2; rh++) {
                float s = 0.f;
#pragma unroll
                for (int nj = 0; nj < 2; nj++) {
#pragma unroll
                    for (int jj = 0; jj < 2; jj++) {
#pragma unroll
                        for (int q = 0; q < 2; q++) {
                            int f = np * 128 + wid * 32 + nj * 16 + jj * 8 +
                                    ((lane & 3) << 1) + q;
                            float z = ws_s[f] + acc[mi][nj * 2 + jj][rh * 2 + q];
                            z = fminf(fmaxf(z, -15.f), 15.f);
                            float e2 = __expf(2.f * z);
                            float x = __fdividef(e2 - 1.f, e2 + 1.f);
                            s = fmaf(V_s[f], x, s);
                        }
                    }
                }
                s += __shfl_xor_sync(0xffffffffu, s, 1);
                s += __shfl_xor_sync(0xffffffffu, s, 2);
                if ((lane & 3) == 0)
                    en_s[(wid << 6) + mi * 16 + rh * 8 + (lane >> 2)] += s;
            }
        }
    }

    // ---------------- finalize energy ----------------
    __syncthreads();
    if (tid < MTILE) {
        float e = Vb[0];
#pragma unroll
        for (int w = 0; w < 4; w++) e += en_s[(w << 6) + tid];
        enf_s[tid] = e;
    }
    __syncthreads();

    // ---------------- context partial: sum_m energy[m] * h[m, e] --------------
    {
        const float4* h4 = reinterpret_cast<const float4*>(hB);
        float4 a0 = make_float4(0.f, 0.f, 0.f, 0.f);
        float4 a1 = make_float4(0.f, 0.f, 0.f, 0.f);
#pragma unroll 8
        for (int m = 0; m < MTILE; m++) {
            float en = enf_s[m];
            float4 v0 = h4[m * 256 + tid * 2];
            float4 v1 = h4[m * 256 + tid * 2 + 1];
            a0.x = fmaf(en, v0.x, a0.x); a0.y = fmaf(en, v0.y, a0.y);
            a0.z = fmaf(en, v0.z, a0.z); a0.w = fmaf(en, v0.w, a0.w);
            a1.x = fmaf(en, v1.x, a1.x); a1.y = fmaf(en, v1.y, a1.y);
            a1.z = fmaf(en, v1.z, a1.z); a1.w = fmaf(en, v1.w, a1.w);
        }
        float4* gp = reinterpret_cast<float4*>(g_partial) +
                     ((size_t)blockIdx.x << 8);
        gp[tid * 2]     = a0;
        gp[tid * 2 + 1] = a1;
    }

    // ---------------- last CTA per batch reduces (deterministic order) --------
    __threadfence();
    if (tid == 0) {
        int old = atomicAdd(&g_cnt[b], 1);
        *flag = (old == NTILES - 1) ? 1 : 0;
    }
    __syncthreads();
    if (*flag) {
        __threadfence();
        const float4* gp = reinterpret_cast<const float4*>(
            g_partial + ((size_t)b * NTILES) * KDIM);
        float4 a0 = make_float4(0.f, 0.f, 0.f, 0.f);
        float4 a1 = make_float4(0.f, 0.f, 0.f, 0.f);
#pragma unroll 8
        for (int tt = 0; tt < NTILES; tt++) {
            float4 v0 = gp[tt * 256 + tid * 2];
            float4 v1 = gp[tt * 256 + tid * 2 + 1];
            a0.x += v0.x; a0.y += v0.y; a0.z += v0.z; a0.w += v0.w;
            a1.x += v1.x; a1.y += v1.y; a1.z += v1.z; a1.w += v1.w;
        }
        float4* o4 = reinterpret_cast<float4*>(out) + b * 256;
        o4[tid * 2]     = a0;
        o4[tid * 2 + 1] = a1;
    }
}

// ---------------------------------------------------------------------------
extern "C" void kernel_launch(void* const* d_in, const int* in_sizes, int n_in,
                              void* d_out, int out_size) {
    (void)in_sizes; (void)n_in; (void)out_size;
    const float* s  = (const float*)d_in[0];
    const float* h  = (const float*)d_in[1];
    const float* Ww = (const float*)d_in[2];
    const float* Wb = (const float*)d_in[3];
    const float* Uw = (const float*)d_in[4];
    const float* Ub = (const float*)d_in[5];
    const float* Vw = (const float*)d_in[6];
    const float* Vb = (const float*)d_in[7];
    float* out = (float*)d_out;

    cudaFuncSetAttribute(k_main, cudaFuncAttributeMaxDynamicSharedMemorySize,
                         SMEM_TOTAL);

    k_prep<<<577, 256>>>(Uw, s, Ww, Wb, Ub);
    k_main<<<NCTAS, 128, SMEM_TOTAL>>>(h, Vw, Vb, out);
}

// round 15
// speedup vs baseline: 1.4059x; 1.4059x over previous
#include <cuda_runtime.h>
#include <cuda_fp16.h>
#include <cstdint>

// ---------------------------------------------------------------------------
// B=32, T=4096, K=1024 (2H), N=512 (DFF)
// HMMA GEMM, 2 CTAs/SM, 128 threads: warp tile M64 x N64, 2 N-passes of 256.
// R15: R8 k_main verbatim (best, 409.7us) + fast smem-tiled prep.
// ---------------------------------------------------------------------------
#define BATCH   32
#define TSEQ    4096
#define KDIM    1024
#define NDFF    512
#define MTILE   64
#define KCH     32
#define NCHUNKS 32
#define NTILES  (TSEQ / MTILE)     // 64
#define NCTAS   (BATCH * NTILES)   // 2048

__device__ __align__(128) __half g_Uh[NDFF * KDIM];             // 1 MB fp16 U [f][e]
__device__ __align__(128) float  g_ws[BATCH * NDFF];
__device__ __align__(128) float  g_partial[NCTAS * KDIM];       // 8 MB
__device__ int g_cnt[BATCH];

// Shared layout (bytes)
#define SM_WS   0                       // 512 f
#define SM_V    2048                    // 512 f
#define SM_EN   4096                    // 4*64 f
#define SM_ENF  5120                    // 64 f
#define SM_FLAG 5376                    // int
#define SM_A    8192                    // 3 stages x 4096
#define SM_B    20480                   // 3 stages x 16384
#define SMEM_TOTAL 69632

#define SWZ(off) ((uint32_t)(off) ^ ((((uint32_t)(off)) >> 3) & 0x70u))

__device__ __forceinline__ uint32_t smem_u32(const void* p) {
    uint32_t a;
    asm("{ .reg .u64 t; cvta.to.shared.u64 t, %1; cvt.u32.u64 %0, t; }"
        : "=r"(a) : "l"(p));
    return a;
}
__device__ __forceinline__ void cp_async16(uint32_t dst, const void* src) {
    asm volatile("cp.async.cg.shared.global [%0], [%1], 16;"
                 :: "r"(dst), "l"(src) : "memory");
}
#define CP_COMMIT() asm volatile("cp.async.commit_group;" ::: "memory")
#define CP_WAIT1()  asm volatile("cp.async.wait_group 1;" ::: "memory")

__device__ __forceinline__ void ldsm4(uint32_t& r0, uint32_t& r1, uint32_t& r2,
                                      uint32_t& r3, uint32_t addr) {
    asm volatile("ldmatrix.sync.aligned.m8n8.x4.shared.b16 {%0,%1,%2,%3}, [%4];"
                 : "=r"(r0), "=r"(r1), "=r"(r2), "=r"(r3) : "r"(addr));
}
__device__ __forceinline__ void mma16816(float* c, const uint32_t* a,
                                         uint32_t b0, uint32_t b1) {
    asm volatile(
        "mma.sync.aligned.m16n8k16.row.col.f32.f16.f16.f32 "
        "{%0,%1,%2,%3}, {%4,%5,%6,%7}, {%8,%9}, {%0,%1,%2,%3};"
        : "+f"(c[0]), "+f"(c[1]), "+f"(c[2]), "+f"(c[3])
        : "r"(a[0]), "r"(a[1]), "r"(a[2]), "r"(a[3]), "r"(b0), "r"(b1));
}
__device__ __forceinline__ uint4 cvt8(const float4& x, const float4& y) {
    uint4 u; __half2 t;
    t = __floats2half2_rn(x.x, x.y); u.x = *(uint32_t*)&t;
    t = __floats2half2_rn(x.z, x.w); u.y = *(uint32_t*)&t;
    t = __floats2half2_rn(y.x, y.y); u.z = *(uint32_t*)&t;
    t = __floats2half2_rn(y.z, y.w); u.w = *(uint32_t*)&t;
    return u;
}

// ---------------------------------------------------------------------------
// Fused prep: blocks 0..511 convU, 512..527 ws (smem-tiled), 528 counters
// ---------------------------------------------------------------------------
#define WPAD 133
__global__ void k_prep(const float* __restrict__ Uw, const float* __restrict__ s,
                       const float* __restrict__ W,  const float* __restrict__ Wb,
                       const float* __restrict__ Ub) {
    int blk = blockIdx.x;
    int tid = threadIdx.x;
    if (blk < 512) {
        int i = blk * 256 + tid;
        float4 v = reinterpret_cast<const float4*>(Uw)[i];
        __half2 p0 = __floats2half2_rn(v.x, v.y);
        __half2 p1 = __floats2half2_rn(v.z, v.w);
        uint2 u;
        u.x = *reinterpret_cast<uint32_t*>(&p0);
        u.y = *reinterpret_cast<uint32_t*>(&p1);
        *reinterpret_cast<uint2*>(&g_Uh[i * 4]) = u;
    } else if (blk < 528) {
        // ws[b][f] for f in [q*32, q*32+32), all 32 b. W read once globally.
        __shared__ float sW[32][WPAD];
        __shared__ float ss[32][WPAD];
        const int q  = blk - 512;
        const int f0 = q * 32;
        const int b  = tid & 31;          // lane
        const int wq = tid >> 5;          // 0..7
        float acc[4];
#pragma unroll
        for (int p = 0; p < 4; p++) {
            int fl = wq * 4 + p;
            acc[p] = Wb[f0 + fl] + Ub[f0 + fl];
        }
#pragma unroll 1
        for (int kt = 0; kt < 4; kt++) {
            // load W tile [32f x 128k] and s tile [32b x 128k]
#pragma unroll
            for (int n = 0; n < 4; n++) {
                int idx = tid + n * 256;          // 0..1023 float4s
                int rr  = idx >> 5;               // 0..31
                int c4  = idx & 31;               // 0..31
                float4 wv = *reinterpret_cast<const float4*>(
                    W + (size_t)(f0 + rr) * 512 + kt * 128 + c4 * 4);
                float4 sv = *reinterpret_cast<const float4*>(
                    s + (size_t)rr * 512 + kt * 128 + c4 * 4);
                sW[rr][c4 * 4 + 0] = wv.x; sW[rr][c4 * 4 + 1] = wv.y;
                sW[rr][c4 * 4 + 2] = wv.z; sW[rr][c4 * 4 + 3] = wv.w;
                ss[rr][c4 * 4 + 0] = sv.x; ss[rr][c4 * 4 + 1] = sv.y;
                ss[rr][c4 * 4 + 2] = sv.z; ss[rr][c4 * 4 + 3] = sv.w;
            }
            __syncthreads();
#pragma unroll 4
            for (int k = 0; k < 128; k++) {
                float sv = ss[b][k];
#pragma unroll
                for (int p = 0; p < 4; p++)
                    acc[p] = fmaf(sv, sW[wq * 4 + p][k], acc[p]);
            }
            __syncthreads();
        }
#pragma unroll
        for (int p = 0; p < 4; p++)
            g_ws[b * 512 + f0 + wq * 4 + p] = acc[p];
    } else {
        if (tid < BATCH) g_cnt[tid] = 0;
    }
}

// ---------------------------------------------------------------------------
// Main kernel (R8 verbatim): 128 threads, 4 warps, warp tile M64 x N64,
// 2 CTAs/SM. Packed smem rows: two 64B k-rows per 128B row, SW128-swizzled.
// ---------------------------------------------------------------------------
__global__ __launch_bounds__(128, 2)
void k_main(const float* __restrict__ h, const float* __restrict__ V,
            const float* __restrict__ Vb, float* __restrict__ out) {
    extern __shared__ char smem[];
    const uint32_t sb = smem_u32(smem);
    const int tid  = threadIdx.x;
    const int wid  = tid >> 5;     // = ng, 0..3
    const int lane = tid & 31;
    const int b    = blockIdx.x >> 6;

    float* ws_s  = reinterpret_cast<float*>(smem + SM_WS);
    float* V_s   = reinterpret_cast<float*>(smem + SM_V);
    float* en_s  = reinterpret_cast<float*>(smem + SM_EN);
    float* enf_s = reinterpret_cast<float*>(smem + SM_ENF);
    int*   flag  = reinterpret_cast<int*>(smem + SM_FLAG);

    for (int i = tid; i < NDFF; i += 128) {
        ws_s[i] = g_ws[b * NDFF + i];
        V_s[i]  = V[i];
    }
    for (int i = tid; i < 4 * MTILE; i += 128) en_s[i] = 0.f;

    const float* hB = h + (size_t)blockIdx.x * (MTILE * KDIM);

    // A stream map
    const int m_0 = tid >> 2, seg = tid & 3;
    const uint32_t a_sts0 = SWZ((m_0 >> 1) * 128 + (m_0 & 1) * 64 + seg * 16);
    const float4* ap0 = reinterpret_cast<const float4*>(hB) + m_0 * 256 + seg * 2;
    const float4* ap1 = ap0 + 32 * 256;

    // B cp.async map
    const uint32_t bdst0 = a_sts0;
    const uint32_t bsrc0 = (uint32_t)(m_0 * KDIM + seg * 8);

    // ldsm bases (XOR-incremental)
    const int r = lane & 7;
    const int selA = (lane >> 3) & 1, selK = (lane >> 4) & 1;
    const int m0f = selA * 8 + r;
    const uint32_t abase0 = SWZ((m0f >> 1) * 128 + (m0f & 1) * 64 + selK * 16);
    const int selKb = (lane >> 3) & 1, selNb = (lane >> 4) & 1;
    const int f0f = selNb * 8 + r;
    const uint32_t bbase0 = SWZ((f0f >> 1) * 128 + (f0f & 1) * 64 + selKb * 16)
                            + (uint32_t)wid * 4096;

    float4 p00, p01, p10, p11;

    // ======================= two N-passes of 256 =======================
#pragma unroll 1
    for (int np = 0; np < 2; np++) {
        const __half* Ub2 = g_Uh + (size_t)(np * 256) * KDIM;

        float acc[4][8][4];
#pragma unroll
        for (int mi = 0; mi < 4; mi++)
#pragma unroll
            for (int ni = 0; ni < 8; ni++)
#pragma unroll
                for (int q = 0; q < 4; q++) acc[mi][ni][q] = 0.f;

        __syncthreads();

        // prologue: A chunks 0,1 -> stages 0,1; chunk 2 in regs; B chunks 0,1
        p00 = ap0[0];  p01 = ap0[1];  p10 = ap1[0];  p11 = ap1[1];
        *reinterpret_cast<uint4*>(smem + SM_A + a_sts0)        = cvt8(p00, p01);
        *reinterpret_cast<uint4*>(smem + SM_A + a_sts0 + 2048) = cvt8(p10, p11);
        p00 = ap0[8];  p01 = ap0[9];  p10 = ap1[8];  p11 = ap1[9];
        *reinterpret_cast<uint4*>(smem + SM_A + 4096 + a_sts0)        = cvt8(p00, p01);
        *reinterpret_cast<uint4*>(smem + SM_A + 4096 + a_sts0 + 2048) = cvt8(p10, p11);
        p00 = ap0[16]; p01 = ap0[17]; p10 = ap1[16]; p11 = ap1[17];
#pragma unroll
        for (int c = 0; c < 2; c++) {
            uint32_t dst = sb + SM_B + c * 16384 + bdst0;
            const __half* src = Ub2 + bsrc0 + c * KCH;
#pragma unroll
            for (int it = 0; it < 8; it++)
                cp_async16(dst + it * 2048, src + it * (32 * KDIM));
            CP_COMMIT();
        }

        // ---------------- K mainloop (fragment-pipelined) ----------------
#pragma unroll 1
        for (int c = 0; c < NCHUNKS; c++) {
            CP_WAIT1();
            __syncthreads();

            const uint32_t ab  = sb + SM_A + (c % 3) * 4096;
            const uint32_t bbs = sb + SM_B + (c % 3) * 16384;

            // fragment prologue: A[ki=0] (4x) and B[ki=0,nj=0]
            uint32_t af[2][4][4];
            uint32_t bf[2][4];
#pragma unroll
            for (int mi = 0; mi < 4; mi++)
                ldsm4(af[0][mi][0], af[0][mi][1], af[0][mi][2], af[0][mi][3],
                      ab + (abase0 + mi * 1024));
            ldsm4(bf[0][0], bf[0][1], bf[0][2], bf[0][3], bbs + bbase0);

            // overlap: issue gmem prefetch for chunk c+2 under ldsm latency
            if (c + 2 < NCHUNKS) {
                const int st = (c + 2) % 3;
                uint32_t dst = sb + SM_B + st * 16384 + bdst0;
                const __half* src = Ub2 + bsrc0 + (c + 2) * KCH;
#pragma unroll
                for (int it = 0; it < 8; it++)
                    cp_async16(dst + it * 2048, src + it * (32 * KDIM));
                *reinterpret_cast<uint4*>(smem + SM_A + st * 4096 + a_sts0)
                    = cvt8(p00, p01);
                *reinterpret_cast<uint4*>(smem + SM_A + st * 4096 + a_sts0 + 2048)
                    = cvt8(p10, p11);
                if (c + 3 < NCHUNKS) {
                    p00 = ap0[(c + 3) * 8];     p01 = ap0[(c + 3) * 8 + 1];
                    p10 = ap1[(c + 3) * 8];     p11 = ap1[(c + 3) * 8 + 1];
                }
            }
            CP_COMMIT();

            // pipelined MMA stream: prefetch next B (or next-ki A+B) before use
#pragma unroll
            for (int ki = 0; ki < 2; ki++) {
                const uint32_t kx = (uint32_t)ki * 32;
#pragma unroll
                for (int nj = 0; nj < 4; nj++) {
                    const int cur = nj & 1;
                    const int nxt = cur ^ 1;
                    if (nj < 3) {
                        ldsm4(bf[nxt][0], bf[nxt][1], bf[nxt][2], bf[nxt][3],
                              bbs + ((bbase0 + (nj + 1) * 1024) ^ kx));
                    } else if (ki == 0) {
#pragma unroll
                        for (int mi = 0; mi < 4; mi++)
                            ldsm4(af[1][mi][0], af[1][mi][1],
                                  af[1][mi][2], af[1][mi][3],
                                  ab + ((abase0 + mi * 1024) ^ 32u));
                        ldsm4(bf[nxt][0], bf[nxt][1], bf[nxt][2], bf[nxt][3],
                              bbs + (bbase0 ^ 32u));
                    }
#pragma unroll
                    for (int mi = 0; mi < 4; mi++) {
                        mma16816(acc[mi][2 * nj],     af[ki][mi], bf[cur][0], bf[cur][1]);
                        mma16816(acc[mi][2 * nj + 1], af[ki][mi], bf[cur][2], bf[cur][3]);
                    }
                }
            }
        }

        // ---------------- epilogue: energy partials ----------------
#pragma unroll
        for (int mi = 0; mi < 4; mi++) {
#pragma unroll
            for (int rh = 0; rh < 2; rh++) {
                float s = 0.f;
#pragma unroll
                for (int nj = 0; nj < 4; nj++) {
#pragma unroll
                    for (int jj = 0; jj < 2; jj++) {
#pragma unroll
                        for (int q = 0; q < 2; q++) {
                            int f = np * 256 + wid * 64 + nj * 16 + jj * 8 +
                                    ((lane & 3) << 1) + q;
                            float z = ws_s[f] + acc[mi][nj * 2 + jj][rh * 2 + q];
                            z = fminf(fmaxf(z, -15.f), 15.f);
                            float e2 = __expf(2.f * z);
                            float x = __fdividef(e2 - 1.f, e2 + 1.f);
                            s = fmaf(V_s[f], x, s);
                        }
                    }
                }
                s += __shfl_xor_sync(0xffffffffu, s, 1);
                s += __shfl_xor_sync(0xffffffffu, s, 2);
                if ((lane & 3) == 0)
                    en_s[(wid << 6) + mi * 16 + rh * 8 + (lane >> 2)] += s;
            }
        }
    }

    // ---------------- finalize energy ----------------
    __syncthreads();
    if (tid < MTILE) {
        float e = Vb[0];
#pragma unroll
        for (int w = 0; w < 4; w++) e += en_s[(w << 6) + tid];
        enf_s[tid] = e;
    }
    __syncthreads();

    // ---------------- context partial: sum_m energy[m] * h[m, e] --------------
    {
        const float4* h4 = reinterpret_cast<const float4*>(hB);
        float4 a0 = make_float4(0.f, 0.f, 0.f, 0.f);
        float4 a1 = make_float4(0.f, 0.f, 0.f, 0.f);
#pragma unroll 8
        for (int m = 0; m < MTILE; m++) {
            float en = enf_s[m];
            float4 v0 = h4[m * 256 + tid * 2];
            float4 v1 = h4[m * 256 + tid * 2 + 1];
            a0.x = fmaf(en, v0.x, a0.x); a0.y = fmaf(en, v0.y, a0.y);
            a0.z = fmaf(en, v0.z, a0.z); a0.w = fmaf(en, v0.w, a0.w);
            a1.x = fmaf(en, v1.x, a1.x); a1.y = fmaf(en, v1.y, a1.y);
            a1.z = fmaf(en, v1.z, a1.z); a1.w = fmaf(en, v1.w, a1.w);
        }
        float4* gp = reinterpret_cast<float4*>(g_partial) +
                     ((size_t)blockIdx.x << 8);
        gp[tid * 2]     = a0;
        gp[tid * 2 + 1] = a1;
    }

    // ---------------- last CTA per batch reduces (deterministic order) --------
    __threadfence();
    if (tid == 0) {
        int old = atomicAdd(&g_cnt[b], 1);
        *flag = (old == NTILES - 1) ? 1 : 0;
    }
    __syncthreads();
    if (*flag) {
        __threadfence();
        const float4* gp = reinterpret_cast<const float4*>(
            g_partial + ((size_t)b * NTILES) * KDIM);
        float4 a0 = make_float4(0.f, 0.f, 0.f, 0.f);
        float4 a1 = make_float4(0.f, 0.f, 0.f, 0.f);
#pragma unroll 8
        for (int tt = 0; tt < NTILES; tt++) {
            float4 v0 = gp[tt * 256 + tid * 2];
            float4 v1 = gp[tt * 256 + tid * 2 + 1];
            a0.x += v0.x; a0.y += v0.y; a0.z += v0.z; a0.w += v0.w;
            a1.x += v1.x; a1.y += v1.y; a1.z += v1.z; a1.w += v1.w;
        }
        float4* o4 = reinterpret_cast<float4*>(out) + b * 256;
        o4[tid * 2]     = a0;
        o4[tid * 2 + 1] = a1;
    }
}

// ---------------------------------------------------------------------------
extern "C" void kernel_launch(void* const* d_in, const int* in_sizes, int n_in,
                              void* d_out, int out_size) {
    (void)in_sizes; (void)n_in; (void)out_size;
    const float* s  = (const float*)d_in[0];
    const float* h  = (const float*)d_in[1];
    const float* Ww = (const float*)d_in[2];
    const float* Wb = (const float*)d_in[3];
    const float* Uw = (const float*)d_in[4];
    const float* Ub = (const float*)d_in[5];
    const float* Vw = (const float*)d_in[6];
    const float* Vb = (const float*)d_in[7];
    float* out = (float*)d_out;

    cudaFuncSetAttribute(k_main, cudaFuncAttributeMaxDynamicSharedMemorySize,
                         SMEM_TOTAL);

    k_prep<<<529, 256>>>(Uw, s, Ww, Wb, Ub);
    k_main<<<NCTAS, 128, SMEM_TOTAL>>>(h, Vw, Vb, out);
}

// round 16
// speedup vs baseline: 1.4326x; 1.0190x over previous
#include <cuda_runtime.h>
#include <cuda_fp16.h>
#include <cstdint>

// ---------------------------------------------------------------------------
// B=32, T=4096, K=1024 (2H), N=512 (DFF)
// HMMA GEMM, 2 CTAs/SM, 128 threads: warp tile M64 x N64, 2 N-passes of 256.
// R16: R8 k_main (best, 409.7us) + k-split partial-ws prep (deterministic).
// ---------------------------------------------------------------------------
#define BATCH   32
#define TSEQ    4096
#define KDIM    1024
#define NDFF    512
#define MTILE   64
#define KCH     32
#define NCHUNKS 32
#define NTILES  (TSEQ / MTILE)     // 64
#define NCTAS   (BATCH * NTILES)   // 2048

__device__ __align__(128) __half g_Uh[NDFF * KDIM];             // 1 MB fp16 U [f][e]
__device__ __align__(128) float  g_wsp[4][BATCH * NDFF];        // ws k-partials
__device__ __align__(128) float  g_partial[NCTAS * KDIM];       // 8 MB
__device__ int g_cnt[BATCH];

// Shared layout (bytes)
#define SM_WS   0                       // 512 f
#define SM_V    2048                    // 512 f
#define SM_EN   4096                    // 4*64 f
#define SM_ENF  5120                    // 64 f
#define SM_FLAG 5376                    // int
#define SM_A    8192                    // 3 stages x 4096
#define SM_B    20480                   // 3 stages x 16384
#define SMEM_TOTAL 69632

#define SWZ(off) ((uint32_t)(off) ^ ((((uint32_t)(off)) >> 3) & 0x70u))

__device__ __forceinline__ uint32_t smem_u32(const void* p) {
    uint32_t a;
    asm("{ .reg .u64 t; cvta.to.shared.u64 t, %1; cvt.u32.u64 %0, t; }"
        : "=r"(a) : "l"(p));
    return a;
}
__device__ __forceinline__ void cp_async16(uint32_t dst, const void* src) {
    asm volatile("cp.async.cg.shared.global [%0], [%1], 16;"
                 :: "r"(dst), "l"(src) : "memory");
}
#define CP_COMMIT() asm volatile("cp.async.commit_group;" ::: "memory")
#define CP_WAIT1()  asm volatile("cp.async.wait_group 1;" ::: "memory")

__device__ __forceinline__ void ldsm4(uint32_t& r0, uint32_t& r1, uint32_t& r2,
                                      uint32_t& r3, uint32_t addr) {
    asm volatile("ldmatrix.sync.aligned.m8n8.x4.shared.b16 {%0,%1,%2,%3}, [%4];"
                 : "=r"(r0), "=r"(r1), "=r"(r2), "=r"(r3) : "r"(addr));
}
__device__ __forceinline__ void mma16816(float* c, const uint32_t* a,
                                         uint32_t b0, uint32_t b1) {
    asm volatile(
        "mma.sync.aligned.m16n8k16.row.col.f32.f16.f16.f32 "
        "{%0,%1,%2,%3}, {%4,%5,%6,%7}, {%8,%9}, {%0,%1,%2,%3};"
        : "+f"(c[0]), "+f"(c[1]), "+f"(c[2]), "+f"(c[3])
        : "r"(a[0]), "r"(a[1]), "r"(a[2]), "r"(a[3]), "r"(b0), "r"(b1));
}
__device__ __forceinline__ uint4 cvt8(const float4& x, const float4& y) {
    uint4 u; __half2 t;
    t = __floats2half2_rn(x.x, x.y); u.x = *(uint32_t*)&t;
    t = __floats2half2_rn(x.z, x.w); u.y = *(uint32_t*)&t;
    t = __floats2half2_rn(y.x, y.y); u.z = *(uint32_t*)&t;
    t = __floats2half2_rn(y.z, y.w); u.w = *(uint32_t*)&t;
    return u;
}

// ---------------------------------------------------------------------------
// Fused prep: blocks 0..511 convU; 512..575 ws k-partials; 576 counters.
// ws block p = blk-512: q = p>>2 selects f-range [q*32,q*32+32), kt = p&3
// selects k-range [kt*128, kt*128+128). Unique writer per output cell.
// ---------------------------------------------------------------------------
#define WPAD 133
__global__ void k_prep(const float* __restrict__ Uw, const float* __restrict__ s,
                       const float* __restrict__ W,  const float* __restrict__ Wb,
                       const float* __restrict__ Ub) {
    int blk = blockIdx.x;
    int tid = threadIdx.x;
    if (blk < 512) {
        int i = blk * 256 + tid;
        float4 v = reinterpret_cast<const float4*>(Uw)[i];
        __half2 p0 = __floats2half2_rn(v.x, v.y);
        __half2 p1 = __floats2half2_rn(v.z, v.w);
        uint2 u;
        u.x = *reinterpret_cast<uint32_t*>(&p0);
        u.y = *reinterpret_cast<uint32_t*>(&p1);
        *reinterpret_cast<uint2*>(&g_Uh[i * 4]) = u;
    } else if (blk < 576) {
        __shared__ float sW[32][WPAD];
        __shared__ float ss[32][WPAD];
        const int p  = blk - 512;
        const int q  = p >> 2;            // f-chunk 0..15
        const int kt = p & 3;             // k-tile 0..3
        const int f0 = q * 32;
        const int b  = tid & 31;          // lane = batch
        const int wq = tid >> 5;          // 0..7

        // load W tile [32f x 128k] and s tile [32b x 128k]
#pragma unroll
        for (int n = 0; n < 4; n++) {
            int idx = tid + n * 256;              // 0..1023 float4s
            int rr  = idx >> 5;                   // 0..31
            int c4  = idx & 31;                   // 0..31
            float4 wv = *reinterpret_cast<const float4*>(
                W + (size_t)(f0 + rr) * 512 + kt * 128 + c4 * 4);
            float4 sv = *reinterpret_cast<const float4*>(
                s + (size_t)rr * 512 + kt * 128 + c4 * 4);
            sW[rr][c4 * 4 + 0] = wv.x; sW[rr][c4 * 4 + 1] = wv.y;
            sW[rr][c4 * 4 + 2] = wv.z; sW[rr][c4 * 4 + 3] = wv.w;
            ss[rr][c4 * 4 + 0] = sv.x; ss[rr][c4 * 4 + 1] = sv.y;
            ss[rr][c4 * 4 + 2] = sv.z; ss[rr][c4 * 4 + 3] = sv.w;
        }
        __syncthreads();

        float acc[4];
#pragma unroll
        for (int pq = 0; pq < 4; pq++) {
            int fl = wq * 4 + pq;
            acc[pq] = (kt == 0) ? (Wb[f0 + fl] + Ub[f0 + fl]) : 0.f;
        }
#pragma unroll 4
        for (int k = 0; k < 128; k++) {
            float sv = ss[b][k];
#pragma unroll
            for (int pq = 0; pq < 4; pq++)
                acc[pq] = fmaf(sv, sW[wq * 4 + pq][k], acc[pq]);
        }
#pragma unroll
        for (int pq = 0; pq < 4; pq++)
            g_wsp[kt][b * 512 + f0 + wq * 4 + pq] = acc[pq];
    } else {
        if (tid < BATCH) g_cnt[tid] = 0;
    }
}

// ---------------------------------------------------------------------------
// Main kernel (R8): 128 threads, 4 warps, warp tile M64 x N64, 2 CTAs/SM.
// Packed smem rows: two 64B k-rows per 128B row, SW128-swizzled.
// ---------------------------------------------------------------------------
__global__ __launch_bounds__(128, 2)
void k_main(const float* __restrict__ h, const float* __restrict__ V,
            const float* __restrict__ Vb, float* __restrict__ out) {
    extern __shared__ char smem[];
    const uint32_t sb = smem_u32(smem);
    const int tid  = threadIdx.x;
    const int wid  = tid >> 5;     // = ng, 0..3
    const int lane = tid & 31;
    const int b    = blockIdx.x >> 6;

    float* ws_s  = reinterpret_cast<float*>(smem + SM_WS);
    float* V_s   = reinterpret_cast<float*>(smem + SM_V);
    float* en_s  = reinterpret_cast<float*>(smem + SM_EN);
    float* enf_s = reinterpret_cast<float*>(smem + SM_ENF);
    int*   flag  = reinterpret_cast<int*>(smem + SM_FLAG);

    for (int i = tid; i < NDFF; i += 128) {
        int o = b * NDFF + i;
        ws_s[i] = (g_wsp[0][o] + g_wsp[1][o]) + (g_wsp[2][o] + g_wsp[3][o]);
        V_s[i]  = V[i];
    }
    for (int i = tid; i < 4 * MTILE; i += 128) en_s[i] = 0.f;

    const float* hB = h + (size_t)blockIdx.x * (MTILE * KDIM);

    // A stream map
    const int m_0 = tid >> 2, seg = tid & 3;
    const uint32_t a_sts0 = SWZ((m_0 >> 1) * 128 + (m_0 & 1) * 64 + seg * 16);
    const float4* ap0 = reinterpret_cast<const float4*>(hB) + m_0 * 256 + seg * 2;
    const float4* ap1 = ap0 + 32 * 256;

    // B cp.async map
    const uint32_t bdst0 = a_sts0;
    const uint32_t bsrc0 = (uint32_t)(m_0 * KDIM + seg * 8);

    // ldsm bases (XOR-incremental)
    const int r = lane & 7;
    const int selA = (lane >> 3) & 1, selK = (lane >> 4) & 1;
    const int m0f = selA * 8 + r;
    const uint32_t abase0 = SWZ((m0f >> 1) * 128 + (m0f & 1) * 64 + selK * 16);
    const int selKb = (lane >> 3) & 1, selNb = (lane >> 4) & 1;
    const int f0f = selNb * 8 + r;
    const uint32_t bbase0 = SWZ((f0f >> 1) * 128 + (f0f & 1) * 64 + selKb * 16)
                            + (uint32_t)wid * 4096;

    float4 p00, p01, p10, p11;

    // ======================= two N-passes of 256 =======================
#pragma unroll 1
    for (int np = 0; np < 2; np++) {
        const __half* Ub2 = g_Uh + (size_t)(np * 256) * KDIM;

        float acc[4][8][4];
#pragma unroll
        for (int mi = 0; mi < 4; mi++)
#pragma unroll
            for (int ni = 0; ni < 8; ni++)
#pragma unroll
                for (int q = 0; q < 4; q++) acc[mi][ni][q] = 0.f;

        __syncthreads();

        // prologue: A chunks 0,1 -> stages 0,1; chunk 2 in regs; B chunks 0,1
        p00 = ap0[0];  p01 = ap0[1];  p10 = ap1[0];  p11 = ap1[1];
        *reinterpret_cast<uint4*>(smem + SM_A + a_sts0)        = cvt8(p00, p01);
        *reinterpret_cast<uint4*>(smem + SM_A + a_sts0 + 2048) = cvt8(p10, p11);
        p00 = ap0[8];  p01 = ap0[9];  p10 = ap1[8];  p11 = ap1[9];
        *reinterpret_cast<uint4*>(smem + SM_A + 4096 + a_sts0)        = cvt8(p00, p01);
        *reinterpret_cast<uint4*>(smem + SM_A + 4096 + a_sts0 + 2048) = cvt8(p10, p11);
        p00 = ap0[16]; p01 = ap0[17]; p10 = ap1[16]; p11 = ap1[17];
#pragma unroll
        for (int c = 0; c < 2; c++) {
            uint32_t dst = sb + SM_B + c * 16384 + bdst0;
            const __half* src = Ub2 + bsrc0 + c * KCH;
#pragma unroll
            for (int it = 0; it < 8; it++)
                cp_async16(dst + it * 2048, src + it * (32 * KDIM));
            CP_COMMIT();
        }

        // ---------------- K mainloop (fragment-pipelined) ----------------
#pragma unroll 1
        for (int c = 0; c < NCHUNKS; c++) {
            CP_WAIT1();
            __syncthreads();

            const uint32_t ab  = sb + SM_A + (c % 3) * 4096;
            const uint32_t bbs = sb + SM_B + (c % 3) * 16384;

            // fragment prologue: A[ki=0] (4x) and B[ki=0,nj=0]
            uint32_t af[2][4][4];
            uint32_t bf[2][4];
#pragma unroll
            for (int mi = 0; mi < 4; mi++)
                ldsm4(af[0][mi][0], af[0][mi][1], af[0][mi][2], af[0][mi][3],
                      ab + (abase0 + mi * 1024));
            ldsm4(bf[0][0], bf[0][1], bf[0][2], bf[0][3], bbs + bbase0);

            // overlap: issue gmem prefetch for chunk c+2 under ldsm latency
            if (c + 2 < NCHUNKS) {
                const int st = (c + 2) % 3;
                uint32_t dst = sb + SM_B + st * 16384 + bdst0;
                const __half* src = Ub2 + bsrc0 + (c + 2) * KCH;
#pragma unroll
                for (int it = 0; it < 8; it++)
                    cp_async16(dst + it * 2048, src + it * (32 * KDIM));
                *reinterpret_cast<uint4*>(smem + SM_A + st * 4096 + a_sts0)
                    = cvt8(p00, p01);
                *reinterpret_cast<uint4*>(smem + SM_A + st * 4096 + a_sts0 + 2048)
                    = cvt8(p10, p11);
                if (c + 3 < NCHUNKS) {
                    p00 = ap0[(c + 3) * 8];     p01 = ap0[(c + 3) * 8 + 1];
                    p10 = ap1[(c + 3) * 8];     p11 = ap1[(c + 3) * 8 + 1];
                }
            }
            CP_COMMIT();

            // pipelined MMA stream: prefetch next B (or next-ki A+B) before use
#pragma unroll
            for (int ki = 0; ki < 2; ki++) {
                const uint32_t kx = (uint32_t)ki * 32;
#pragma unroll
                for (int nj = 0; nj < 4; nj++) {
                    const int cur = nj & 1;
                    const int nxt = cur ^ 1;
                    if (nj < 3) {
                        ldsm4(bf[nxt][0], bf[nxt][1], bf[nxt][2], bf[nxt][3],
                              bbs + ((bbase0 + (nj + 1) * 1024) ^ kx));
                    } else if (ki == 0) {
#pragma unroll
                        for (int mi = 0; mi < 4; mi++)
                            ldsm4(af[1][mi][0], af[1][mi][1],
                                  af[1][mi][2], af[1][mi][3],
                                  ab + ((abase0 + mi * 1024) ^ 32u));
                        ldsm4(bf[nxt][0], bf[nxt][1], bf[nxt][2], bf[nxt][3],
                              bbs + (bbase0 ^ 32u));
                    }
#pragma unroll
                    for (int mi = 0; mi < 4; mi++) {
                        mma16816(acc[mi][2 * nj],     af[ki][mi], bf[cur][0], bf[cur][1]);
                        mma16816(acc[mi][2 * nj + 1], af[ki][mi], bf[cur][2], bf[cur][3]);
                    }
                }
            }
        }

        // ---------------- epilogue: energy partials ----------------
#pragma unroll
        for (int mi = 0; mi < 4; mi++) {
#pragma unroll
            for (int rh = 0; rh < 2; rh++) {
                float s = 0.f;
#pragma unroll
                for (int nj = 0; nj < 4; nj++) {
#pragma unroll
                    for (int jj = 0; jj < 2; jj++) {
#pragma unroll
                        for (int q = 0; q < 2; q++) {
                            int f = np * 256 + wid * 64 + nj * 16 + jj * 8 +
                                    ((lane & 3) << 1) + q;
                            float z = ws_s[f] + acc[mi][nj * 2 + jj][rh * 2 + q];
                            z = fminf(fmaxf(z, -15.f), 15.f);
                            float e2 = __expf(2.f * z);
                            float x = __fdividef(e2 - 1.f, e2 + 1.f);
                            s = fmaf(V_s[f], x, s);
                        }
                    }
                }
                s += __shfl_xor_sync(0xffffffffu, s, 1);
                s += __shfl_xor_sync(0xffffffffu, s, 2);
                if ((lane & 3) == 0)
                    en_s[(wid << 6) + mi * 16 + rh * 8 + (lane >> 2)] += s;
            }
        }
    }

    // ---------------- finalize energy ----------------
    __syncthreads();
    if (tid < MTILE) {
        float e = Vb[0];
#pragma unroll
        for (int w = 0; w < 4; w++) e += en_s[(w << 6) + tid];
        enf_s[tid] = e;
    }
    __syncthreads();

    // ---------------- context partial: sum_m energy[m] * h[m, e] --------------
    {
        const float4* h4 = reinterpret_cast<const float4*>(hB);
        float4 a0 = make_float4(0.f, 0.f, 0.f, 0.f);
        float4 a1 = make_float4(0.f, 0.f, 0.f, 0.f);
#pragma unroll 8
        for (int m = 0; m < MTILE; m++) {
            float en = enf_s[m];
            float4 v0 = h4[m * 256 + tid * 2];
            float4 v1 = h4[m * 256 + tid * 2 + 1];
            a0.x = fmaf(en, v0.x, a0.x); a0.y = fmaf(en, v0.y, a0.y);
            a0.z = fmaf(en, v0.z, a0.z); a0.w = fmaf(en, v0.w, a0.w);
            a1.x = fmaf(en, v1.x, a1.x); a1.y = fmaf(en, v1.y, a1.y);
            a1.z = fmaf(en, v1.z, a1.z); a1.w = fmaf(en, v1.w, a1.w);
        }
        float4* gp = reinterpret_cast<float4*>(g_partial) +
                     ((size_t)blockIdx.x << 8);
        gp[tid * 2]     = a0;
        gp[tid * 2 + 1] = a1;
    }

    // ---------------- last CTA per batch reduces (deterministic order) --------
    __threadfence();
    if (tid == 0) {
        int old = atomicAdd(&g_cnt[b], 1);
        *flag = (old == NTILES - 1) ? 1 : 0;
    }
    __syncthreads();
    if (*flag) {
        __threadfence();
        const float4* gp = reinterpret_cast<const float4*>(
            g_partial + ((size_t)b * NTILES) * KDIM);
        float4 a0 = make_float4(0.f, 0.f, 0.f, 0.f);
        float4 a1 = make_float4(0.f, 0.f, 0.f, 0.f);
#pragma unroll 8
        for (int tt = 0; tt < NTILES; tt++) {
            float4 v0 = gp[tt * 256 + tid * 2];
            float4 v1 = gp[tt * 256 + tid * 2 + 1];
            a0.x += v0.x; a0.y += v0.y; a0.z += v0.z; a0.w += v0.w;
            a1.x += v1.x; a1.y += v1.y; a1.z += v1.z; a1.w += v1.w;
        }
        float4* o4 = reinterpret_cast<float4*>(out) + b * 256;
        o4[tid * 2]     = a0;
        o4[tid * 2 + 1] = a1;
    }
}

// ---------------------------------------------------------------------------
extern "C" void kernel_launch(void* const* d_in, const int* in_sizes, int n_in,
                              void* d_out, int out_size) {
    (void)in_sizes; (void)n_in; (void)out_size;
    const float* s  = (const float*)d_in[0];
    const float* h  = (const float*)d_in[1];
    const float* Ww = (const float*)d_in[2];
    const float* Wb = (const float*)d_in[3];
    const float* Uw = (const float*)d_in[4];
    const float* Ub = (const float*)d_in[5];
    const float* Vw = (const float*)d_in[6];
    const float* Vb = (const float*)d_in[7];
    float* out = (float*)d_out;

    cudaFuncSetAttribute(k_main, cudaFuncAttributeMaxDynamicSharedMemorySize,
                         SMEM_TOTAL);

    k_prep<<<577, 256>>>(Uw, s, Ww, Wb, Ub);
    k_main<<<NCTAS, 128, SMEM_TOTAL>>>(h, Vw, Vb, out);
}

// round 17
// speedup vs baseline: 1.4969x; 1.0448x over previous
#include <cuda_runtime.h>
#include <cuda_fp16.h>
#include <cstdint>

// ---------------------------------------------------------------------------
// B=32, T=4096, K=1024 (2H), N=512 (DFF)
// HMMA GEMM, 2 CTAs/SM, 128 threads: warp tile M64 x N64, 2 N-passes of 256.
// R17: R16 + MUFU tanh.approx epilogue (replaces expf/div chain).
// ---------------------------------------------------------------------------
#define BATCH   32
#define TSEQ    4096
#define KDIM    1024
#define NDFF    512
#define MTILE   64
#define KCH     32
#define NCHUNKS 32
#define NTILES  (TSEQ / MTILE)     // 64
#define NCTAS   (BATCH * NTILES)   // 2048

__device__ __align__(128) __half g_Uh[NDFF * KDIM];             // 1 MB fp16 U [f][e]
__device__ __align__(128) float  g_wsp[4][BATCH * NDFF];        // ws k-partials
__device__ __align__(128) float  g_partial[NCTAS * KDIM];       // 8 MB
__device__ int g_cnt[BATCH];

// Shared layout (bytes)
#define SM_WS   0                       // 512 f
#define SM_V    2048                    // 512 f
#define SM_EN   4096                    // 4*64 f
#define SM_ENF  5120                    // 64 f
#define SM_FLAG 5376                    // int
#define SM_A    8192                    // 3 stages x 4096
#define SM_B    20480                   // 3 stages x 16384
#define SMEM_TOTAL 69632

#define SWZ(off) ((uint32_t)(off) ^ ((((uint32_t)(off)) >> 3) & 0x70u))

__device__ __forceinline__ uint32_t smem_u32(const void* p) {
    uint32_t a;
    asm("{ .reg .u64 t; cvta.to.shared.u64 t, %1; cvt.u32.u64 %0, t; }"
        : "=r"(a) : "l"(p));
    return a;
}
__device__ __forceinline__ void cp_async16(uint32_t dst, const void* src) {
    asm volatile("cp.async.cg.shared.global [%0], [%1], 16;"
                 :: "r"(dst), "l"(src) : "memory");
}
#define CP_COMMIT() asm volatile("cp.async.commit_group;" ::: "memory")
#define CP_WAIT1()  asm volatile("cp.async.wait_group 1;" ::: "memory")

__device__ __forceinline__ void ldsm4(uint32_t& r0, uint32_t& r1, uint32_t& r2,
                                      uint32_t& r3, uint32_t addr) {
    asm volatile("ldmatrix.sync.aligned.m8n8.x4.shared.b16 {%0,%1,%2,%3}, [%4];"
                 : "=r"(r0), "=r"(r1), "=r"(r2), "=r"(r3) : "r"(addr));
}
__device__ __forceinline__ void mma16816(float* c, const uint32_t* a,
                                         uint32_t b0, uint32_t b1) {
    asm volatile(
        "mma.sync.aligned.m16n8k16.row.col.f32.f16.f16.f32 "
        "{%0,%1,%2,%3}, {%4,%5,%6,%7}, {%8,%9}, {%0,%1,%2,%3};"
        : "+f"(c[0]), "+f"(c[1]), "+f"(c[2]), "+f"(c[3])
        : "r"(a[0]), "r"(a[1]), "r"(a[2]), "r"(a[3]), "r"(b0), "r"(b1));
}
__device__ __forceinline__ float tanh_hw(float x) {
    float y;
    asm("tanh.approx.f32 %0, %1;" : "=f"(y) : "f"(x));
    return y;
}
__device__ __forceinline__ uint4 cvt8(const float4& x, const float4& y) {
    uint4 u; __half2 t;
    t = __floats2half2_rn(x.x, x.y); u.x = *(uint32_t*)&t;
    t = __floats2half2_rn(x.z, x.w); u.y = *(uint32_t*)&t;
    t = __floats2half2_rn(y.x, y.y); u.z = *(uint32_t*)&t;
    t = __floats2half2_rn(y.z, y.w); u.w = *(uint32_t*)&t;
    return u;
}

// ---------------------------------------------------------------------------
// Fused prep: blocks 0..511 convU; 512..575 ws k-partials; 576 counters.
// ---------------------------------------------------------------------------
#define WPAD 133
__global__ void k_prep(const float* __restrict__ Uw, const float* __restrict__ s,
                       const float* __restrict__ W,  const float* __restrict__ Wb,
                       const float* __restrict__ Ub) {
    int blk = blockIdx.x;
    int tid = threadIdx.x;
    if (blk < 512) {
        int i = blk * 256 + tid;
        float4 v = reinterpret_cast<const float4*>(Uw)[i];
        __half2 p0 = __floats2half2_rn(v.x, v.y);
        __half2 p1 = __floats2half2_rn(v.z, v.w);
        uint2 u;
        u.x = *reinterpret_cast<uint32_t*>(&p0);
        u.y = *reinterpret_cast<uint32_t*>(&p1);
        *reinterpret_cast<uint2*>(&g_Uh[i * 4]) = u;
    } else if (blk < 576) {
        __shared__ float sW[32][WPAD];
        __shared__ float ss[32][WPAD];
        const int p  = blk - 512;
        const int q  = p >> 2;            // f-chunk 0..15
        const int kt = p & 3;             // k-tile 0..3
        const int f0 = q * 32;
        const int b  = tid & 31;          // lane = batch
        const int wq = tid >> 5;          // 0..7

#pragma unroll
        for (int n = 0; n < 4; n++) {
            int idx = tid + n * 256;
            int rr  = idx >> 5;
            int c4  = idx & 31;
            float4 wv = *reinterpret_cast<const float4*>(
                W + (size_t)(f0 + rr) * 512 + kt * 128 + c4 * 4);
            float4 sv = *reinterpret_cast<const float4*>(
                s + (size_t)rr * 512 + kt * 128 + c4 * 4);
            sW[rr][c4 * 4 + 0] = wv.x; sW[rr][c4 * 4 + 1] = wv.y;
            sW[rr][c4 * 4 + 2] = wv.z; sW[rr][c4 * 4 + 3] = wv.w;
            ss[rr][c4 * 4 + 0] = sv.x; ss[rr][c4 * 4 + 1] = sv.y;
            ss[rr][c4 * 4 + 2] = sv.z; ss[rr][c4 * 4 + 3] = sv.w;
        }
        __syncthreads();

        float acc[4];
#pragma unroll
        for (int pq = 0; pq < 4; pq++) {
            int fl = wq * 4 + pq;
            acc[pq] = (kt == 0) ? (Wb[f0 + fl] + Ub[f0 + fl]) : 0.f;
        }
#pragma unroll 4
        for (int k = 0; k < 128; k++) {
            float sv = ss[b][k];
#pragma unroll
            for (int pq = 0; pq < 4; pq++)
                acc[pq] = fmaf(sv, sW[wq * 4 + pq][k], acc[pq]);
        }
#pragma unroll
        for (int pq = 0; pq < 4; pq++)
            g_wsp[kt][b * 512 + f0 + wq * 4 + pq] = acc[pq];
    } else {
        if (tid < BATCH) g_cnt[tid] = 0;
    }
}

// ---------------------------------------------------------------------------
// Main kernel (R8): 128 threads, 4 warps, warp tile M64 x N64, 2 CTAs/SM.
// Packed smem rows: two 64B k-rows per 128B row, SW128-swizzled.
// ---------------------------------------------------------------------------
__global__ __launch_bounds__(128, 2)
void k_main(const float* __restrict__ h, const float* __restrict__ V,
            const float* __restrict__ Vb, float* __restrict__ out) {
    extern __shared__ char smem[];
    const uint32_t sb = smem_u32(smem);
    const int tid  = threadIdx.x;
    const int wid  = tid >> 5;     // = ng, 0..3
    const int lane = tid & 31;
    const int b    = blockIdx.x >> 6;

    float* ws_s  = reinterpret_cast<float*>(smem + SM_WS);
    float* V_s   = reinterpret_cast<float*>(smem + SM_V);
    float* en_s  = reinterpret_cast<float*>(smem + SM_EN);
    float* enf_s = reinterpret_cast<float*>(smem + SM_ENF);
    int*   flag  = reinterpret_cast<int*>(smem + SM_FLAG);

    for (int i = tid; i < NDFF; i += 128) {
        int o = b * NDFF + i;
        ws_s[i] = (g_wsp[0][o] + g_wsp[1][o]) + (g_wsp[2][o] + g_wsp[3][o]);
        V_s[i]  = V[i];
    }
    for (int i = tid; i < 4 * MTILE; i += 128) en_s[i] = 0.f;

    const float* hB = h + (size_t)blockIdx.x * (MTILE * KDIM);

    // A stream map
    const int m_0 = tid >> 2, seg = tid & 3;
    const uint32_t a_sts0 = SWZ((m_0 >> 1) * 128 + (m_0 & 1) * 64 + seg * 16);
    const float4* ap0 = reinterpret_cast<const float4*>(hB) + m_0 * 256 + seg * 2;
    const float4* ap1 = ap0 + 32 * 256;

    // B cp.async map
    const uint32_t bdst0 = a_sts0;
    const uint32_t bsrc0 = (uint32_t)(m_0 * KDIM + seg * 8);

    // ldsm bases (XOR-incremental)
    const int r = lane & 7;
    const int selA = (lane >> 3) & 1, selK = (lane >> 4) & 1;
    const int m0f = selA * 8 + r;
    const uint32_t abase0 = SWZ((m0f >> 1) * 128 + (m0f & 1) * 64 + selK * 16);
    const int selKb = (lane >> 3) & 1, selNb = (lane >> 4) & 1;
    const int f0f = selNb * 8 + r;
    const uint32_t bbase0 = SWZ((f0f >> 1) * 128 + (f0f & 1) * 64 + selKb * 16)
                            + (uint32_t)wid * 4096;

    float4 p00, p01, p10, p11;

    // ======================= two N-passes of 256 =======================
#pragma unroll 1
    for (int np = 0; np < 2; np++) {
        const __half* Ub2 = g_Uh + (size_t)(np * 256) * KDIM;

        float acc[4][8][4];
#pragma unroll
        for (int mi = 0; mi < 4; mi++)
#pragma unroll
            for (int ni = 0; ni < 8; ni++)
#pragma unroll
                for (int q = 0; q < 4; q++) acc[mi][ni][q] = 0.f;

        __syncthreads();

        // prologue: A chunks 0,1 -> stages 0,1; chunk 2 in regs; B chunks 0,1
        p00 = ap0[0];  p01 = ap0[1];  p10 = ap1[0];  p11 = ap1[1];
        *reinterpret_cast<uint4*>(smem + SM_A + a_sts0)        = cvt8(p00, p01);
        *reinterpret_cast<uint4*>(smem + SM_A + a_sts0 + 2048) = cvt8(p10, p11);
        p00 = ap0[8];  p01 = ap0[9];  p10 = ap1[8];  p11 = ap1[9];
        *reinterpret_cast<uint4*>(smem + SM_A + 4096 + a_sts0)        = cvt8(p00, p01);
        *reinterpret_cast<uint4*>(smem + SM_A + 4096 + a_sts0 + 2048) = cvt8(p10, p11);
        p00 = ap0[16]; p01 = ap0[17]; p10 = ap1[16]; p11 = ap1[17];
#pragma unroll
        for (int c = 0; c < 2; c++) {
            uint32_t dst = sb + SM_B + c * 16384 + bdst0;
            const __half* src = Ub2 + bsrc0 + c * KCH;
#pragma unroll
            for (int it = 0; it < 8; it++)
                cp_async16(dst + it * 2048, src + it * (32 * KDIM));
            CP_COMMIT();
        }

        // ---------------- K mainloop (fragment-pipelined) ----------------
#pragma unroll 1
        for (int c = 0; c < NCHUNKS; c++) {
            CP_WAIT1();
            __syncthreads();

            const uint32_t ab  = sb + SM_A + (c % 3) * 4096;
            const uint32_t bbs = sb + SM_B + (c % 3) * 16384;

            // fragment prologue: A[ki=0] (4x) and B[ki=0,nj=0]
            uint32_t af[2][4][4];
            uint32_t bf[2][4];
#pragma unroll
            for (int mi = 0; mi < 4; mi++)
                ldsm4(af[0][mi][0], af[0][mi][1], af[0][mi][2], af[0][mi][3],
                      ab + (abase0 + mi * 1024));
            ldsm4(bf[0][0], bf[0][1], bf[0][2], bf[0][3], bbs + bbase0);

            // overlap: issue gmem prefetch for chunk c+2 under ldsm latency
            if (c + 2 < NCHUNKS) {
                const int st = (c + 2) % 3;
                uint32_t dst = sb + SM_B + st * 16384 + bdst0;
                const __half* src = Ub2 + bsrc0 + (c + 2) * KCH;
#pragma unroll
                for (int it = 0; it < 8; it++)
                    cp_async16(dst + it * 2048, src + it * (32 * KDIM));
                *reinterpret_cast<uint4*>(smem + SM_A + st * 4096 + a_sts0)
                    = cvt8(p00, p01);
                *reinterpret_cast<uint4*>(smem + SM_A + st * 4096 + a_sts0 + 2048)
                    = cvt8(p10, p11);
                if (c + 3 < NCHUNKS) {
                    p00 = ap0[(c + 3) * 8];     p01 = ap0[(c + 3) * 8 + 1];
                    p10 = ap1[(c + 3) * 8];     p11 = ap1[(c + 3) * 8 + 1];
                }
            }
            CP_COMMIT();

            // pipelined MMA stream: prefetch next B (or next-ki A+B) before use
#pragma unroll
            for (int ki = 0; ki < 2; ki++) {
                const uint32_t kx = (uint32_t)ki * 32;
#pragma unroll
                for (int nj = 0; nj < 4; nj++) {
                    const int cur = nj & 1;
                    const int nxt = cur ^ 1;
                    if (nj < 3) {
                        ldsm4(bf[nxt][0], bf[nxt][1], bf[nxt][2], bf[nxt][3],
                              bbs + ((bbase0 + (nj + 1) * 1024) ^ kx));
                    } else if (ki == 0) {
#pragma unroll
                        for (int mi = 0; mi < 4; mi++)
                            ldsm4(af[1][mi][0], af[1][mi][1],
                                  af[1][mi][2], af[1][mi][3],
                                  ab + ((abase0 + mi * 1024) ^ 32u));
                        ldsm4(bf[nxt][0], bf[nxt][1], bf[nxt][2], bf[nxt][3],
                              bbs + (bbase0 ^ 32u));
                    }
#pragma unroll
                    for (int mi = 0; mi < 4; mi++) {
                        mma16816(acc[mi][2 * nj],     af[ki][mi], bf[cur][0], bf[cur][1]);
                        mma16816(acc[mi][2 * nj + 1], af[ki][mi], bf[cur][2], bf[cur][3]);
                    }
                }
            }
        }

        // ---------------- epilogue: energy partials (HW tanh) ----------------
#pragma unroll
        for (int mi = 0; mi < 4; mi++) {
#pragma unroll
            for (int rh = 0; rh < 2; rh++) {
                float s = 0.f;
#pragma unroll
                for (int nj = 0; nj < 4; nj++) {
#pragma unroll
                    for (int jj = 0; jj < 2; jj++) {
#pragma unroll
                        for (int q = 0; q < 2; q++) {
                            int f = np * 256 + wid * 64 + nj * 16 + jj * 8 +
                                    ((lane & 3) << 1) + q;
                            float z = ws_s[f] + acc[mi][nj * 2 + jj][rh * 2 + q];
                            s = fmaf(V_s[f], tanh_hw(z), s);
                        }
                    }
                }
                s += __shfl_xor_sync(0xffffffffu, s, 1);
                s += __shfl_xor_sync(0xffffffffu, s, 2);
                if ((lane & 3) == 0)
                    en_s[(wid << 6) + mi * 16 + rh * 8 + (lane >> 2)] += s;
            }
        }
    }

    // ---------------- finalize energy ----------------
    __syncthreads();
    if (tid < MTILE) {
        float e = Vb[0];
#pragma unroll
        for (int w = 0; w < 4; w++) e += en_s[(w << 6) + tid];
        enf_s[tid] = e;
    }
    __syncthreads();

    // ---------------- context partial: sum_m energy[m] * h[m, e] --------------
    {
        const float4* h4 = reinterpret_cast<const float4*>(hB);
        float4 a0 = make_float4(0.f, 0.f, 0.f, 0.f);
        float4 a1 = make_float4(0.f, 0.f, 0.f, 0.f);
#pragma unroll 8
        for (int m = 0; m < MTILE; m++) {
            float en = enf_s[m];
            float4 v0 = h4[m * 256 + tid * 2];
            float4 v1 = h4[m * 256 + tid * 2 + 1];
            a0.x = fmaf(en, v0.x, a0.x); a0.y = fmaf(en, v0.y, a0.y);
            a0.z = fmaf(en, v0.z, a0.z); a0.w = fmaf(en, v0.w, a0.w);
            a1.x = fmaf(en, v1.x, a1.x); a1.y = fmaf(en, v1.y, a1.y);
            a1.z = fmaf(en, v1.z, a1.z); a1.w = fmaf(en, v1.w, a1.w);
        }
        float4* gp = reinterpret_cast<float4*>(g_partial) +
                     ((size_t)blockIdx.x << 8);
        gp[tid * 2]     = a0;
        gp[tid * 2 + 1] = a1;
    }

    // ---------------- last CTA per batch reduces (deterministic order) --------
    __threadfence();
    if (tid == 0) {
        int old = atomicAdd(&g_cnt[b], 1);
        *flag = (old == NTILES - 1) ? 1 : 0;
    }
    __syncthreads();
    if (*flag) {
        __threadfence();
        const float4* gp = reinterpret_cast<const float4*>(
            g_partial + ((size_t)b * NTILES) * KDIM);
        float4 a0 = make_float4(0.f, 0.f, 0.f, 0.f);
        float4 a1 = make_float4(0.f, 0.f, 0.f, 0.f);
#pragma unroll 8
        for (int tt = 0; tt < NTILES; tt++) {
            float4 v0 = gp[tt * 256 + tid * 2];
            float4 v1 = gp[tt * 256 + tid * 2 + 1];
            a0.x += v0.x; a0.y += v0.y; a0.z += v0.z; a0.w += v0.w;
            a1.x += v1.x; a1.y += v1.y; a1.z += v1.z; a1.w += v1.w;
        }
        float4* o4 = reinterpret_cast<float4*>(out) + b * 256;
        o4[tid * 2]     = a0;
        o4[tid * 2 + 1] = a1;
    }
}

// ---------------------------------------------------------------------------
extern "C" void kernel_launch(void* const* d_in, const int* in_sizes, int n_in,
                              void* d_out, int out_size) {
    (void)in_sizes; (void)n_in; (void)out_size;
    const float* s  = (const float*)d_in[0];
    const float* h  = (const float*)d_in[1];
    const float* Ww = (const float*)d_in[2];
    const float* Wb = (const float*)d_in[3];
    const float* Uw = (const float*)d_in[4];
    const float* Ub = (const float*)d_in[5];
    const float* Vw = (const float*)d_in[6];
    const float* Vb = (const float*)d_in[7];
    float* out = (float*)d_out;

    cudaFuncSetAttribute(k_main, cudaFuncAttributeMaxDynamicSharedMemorySize,
                         SMEM_TOTAL);

    k_prep<<<577, 256>>>(Uw, s, Ww, Wb, Ub);
    k_main<<<NCTAS, 128, SMEM_TOTAL>>>(h, Vw, Vb, out);
}